// round 1
// baseline (speedup 1.0000x reference)
#include <cuda_runtime.h>
#include <math.h>

// Problem constants
#define NROWS 65536
#define DD    512
#define KSPLIT 64
#define KCHUNK (NROWS / KSPLIT)   // 1024
#define NS_ITERS 10
#define INV_TEMP 0.1f             // 1/ZCA_temp

// ---------------------------------------------------------------------------
// Scratch (static device memory -- no allocations anywhere)
// ---------------------------------------------------------------------------
__device__ float g_H[(size_t)NROWS * DD];            // 128 MB: layer pre-whitening activations
__device__ float g_covp[(size_t)KSPLIT * DD * DD];   // 64 MB: split-K partial H^T H
__device__ float g_G[DD * DD];                       // H^T H (raw sums)
__device__ float g_S[DD * DD];                       // spectral-normalized cov
__device__ float g_P[DD * DD];
__device__ float g_Pn[DD * DD];
__device__ float g_T1[DD * DD];
__device__ float g_T2[DD * DD];
__device__ float g_colp[128 * DD];                   // column-sum partials
__device__ float g_mean[DD];
__device__ float g_scalars[4];                       // [0]=tr [1]=1/tr [2]=rsqrt(tr)

// ---------------------------------------------------------------------------
// Big GEMM: C[M,512] = op(A[M,K]) @ B[K,512], 128x128x8 tiles, 8x8/thread
// AMODE: 0 = plain A ; 1 = subtract mean[k] from A element (xc on the fly)
// EPI  : 0 = plain   ; 1 = scale result by scalars[2] (rsqrt(tr))
// M, K multiples of 128/8; N fixed to 512.
// ---------------------------------------------------------------------------
template<int AMODE, int EPI>
__global__ void __launch_bounds__(256)
sgemm128(const float* __restrict__ A, const float* __restrict__ B,
         float* __restrict__ C, int K,
         const float* __restrict__ mean, const float* __restrict__ scalars)
{
    __shared__ float As[8][128];
    __shared__ float Bs[8][128];

    const int tid  = threadIdx.x;
    const int brow = blockIdx.y * 128;
    const int bcol = blockIdx.x * 128;

    const int a_row = tid >> 1;          // 128 rows
    const int a_col = (tid & 1) * 4;     // 8 k-cols via float4
    const int b_row = tid >> 5;          // 8 k-rows
    const int b_col = (tid & 31) * 4;    // 128 n-cols via float4

    const int trow = (tid >> 4) * 8;
    const int tcol = (tid & 15) * 8;

    float acc[8][8] = {};

    const float* Aptr = A + (size_t)(brow + a_row) * K + a_col;
    const float* Bptr = B + (size_t)b_row * DD + bcol + b_col;

    for (int k0 = 0; k0 < K; k0 += 8) {
        float4 av = *(const float4*)(Aptr + k0);
        if (AMODE == 1) {
            av.x -= mean[k0 + a_col + 0];
            av.y -= mean[k0 + a_col + 1];
            av.z -= mean[k0 + a_col + 2];
            av.w -= mean[k0 + a_col + 3];
        }
        As[a_col + 0][a_row] = av.x;
        As[a_col + 1][a_row] = av.y;
        As[a_col + 2][a_row] = av.z;
        As[a_col + 3][a_row] = av.w;
        *(float4*)&Bs[b_row][b_col] = *(const float4*)(Bptr + (size_t)k0 * DD);
        __syncthreads();

#pragma unroll
        for (int kk = 0; kk < 8; kk++) {
            float4 a0 = *(const float4*)&As[kk][trow];
            float4 a1 = *(const float4*)&As[kk][trow + 4];
            float4 b0 = *(const float4*)&Bs[kk][tcol];
            float4 b1 = *(const float4*)&Bs[kk][tcol + 4];
            float ar[8] = {a0.x, a0.y, a0.z, a0.w, a1.x, a1.y, a1.z, a1.w};
            float br[8] = {b0.x, b0.y, b0.z, b0.w, b1.x, b1.y, b1.z, b1.w};
#pragma unroll
            for (int i = 0; i < 8; i++)
#pragma unroll
                for (int j = 0; j < 8; j++)
                    acc[i][j] = fmaf(ar[i], br[j], acc[i][j]);
        }
        __syncthreads();
    }

    const float scale = (EPI == 1) ? scalars[2] : 1.0f;
#pragma unroll
    for (int i = 0; i < 8; i++) {
        const size_t row = (size_t)(brow + trow + i);
#pragma unroll
        for (int j = 0; j < 8; j += 4) {
            float4 v;
            v.x = acc[i][j + 0] * scale;
            v.y = acc[i][j + 1] * scale;
            v.z = acc[i][j + 2] * scale;
            v.w = acc[i][j + 3] * scale;
            *(float4*)&C[row * DD + bcol + tcol + j] = v;
        }
    }
}

// ---------------------------------------------------------------------------
// Split-K covariance GEMM: Cp[z] = H_chunk^T @ H_chunk  (128x128x8 tiles)
// Both operand tiles are loaded [k][d] directly (no transpose needed).
// ---------------------------------------------------------------------------
__global__ void __launch_bounds__(256)
covgemm(const float* __restrict__ H, float* __restrict__ Cp)
{
    __shared__ float As[8][128];
    __shared__ float Bs[8][128];

    const int tid = threadIdx.x;
    const int i0 = blockIdx.y * 128;
    const int j0 = blockIdx.x * 128;
    const int z  = blockIdx.z;

    const int l_row = tid >> 5;          // 8 k-rows
    const int l_col = (tid & 31) * 4;    // 128 d-cols via float4
    const int trow = (tid >> 4) * 8;
    const int tcol = (tid & 15) * 8;

    float acc[8][8] = {};
    const float* Hb = H + (size_t)z * KCHUNK * DD;

    for (int k0 = 0; k0 < KCHUNK; k0 += 8) {
        const float* hrow = Hb + (size_t)(k0 + l_row) * DD;
        *(float4*)&As[l_row][l_col] = *(const float4*)(hrow + i0 + l_col);
        *(float4*)&Bs[l_row][l_col] = *(const float4*)(hrow + j0 + l_col);
        __syncthreads();

#pragma unroll
        for (int kk = 0; kk < 8; kk++) {
            float4 a0 = *(const float4*)&As[kk][trow];
            float4 a1 = *(const float4*)&As[kk][trow + 4];
            float4 b0 = *(const float4*)&Bs[kk][tcol];
            float4 b1 = *(const float4*)&Bs[kk][tcol + 4];
            float ar[8] = {a0.x, a0.y, a0.z, a0.w, a1.x, a1.y, a1.z, a1.w};
            float br[8] = {b0.x, b0.y, b0.z, b0.w, b1.x, b1.y, b1.z, b1.w};
#pragma unroll
            for (int i = 0; i < 8; i++)
#pragma unroll
                for (int j = 0; j < 8; j++)
                    acc[i][j] = fmaf(ar[i], br[j], acc[i][j]);
        }
        __syncthreads();
    }

    float* out = Cp + (size_t)z * DD * DD;
#pragma unroll
    for (int i = 0; i < 8; i++) {
#pragma unroll
        for (int j = 0; j < 8; j += 4) {
            float4 v;
            v.x = acc[i][j + 0];
            v.y = acc[i][j + 1];
            v.z = acc[i][j + 2];
            v.w = acc[i][j + 3];
            *(float4*)&out[(size_t)(i0 + trow + i) * DD + j0 + tcol + j] = v;
        }
    }
}

// Deterministic split-K reduction: G = sum_z Cp[z]
__global__ void reduce_cov(const float* __restrict__ Cp, float* __restrict__ G)
{
    const int idx = blockIdx.x * 512 + threadIdx.x;
    float s = 0.0f;
#pragma unroll 8
    for (int z = 0; z < KSPLIT; z++)
        s += Cp[(size_t)z * DD * DD + idx];
    G[idx] = s;
}

// ---------------------------------------------------------------------------
// Small GEMM: C[512,512] = A @ B, 64x64x16 tiles, 4x4/thread, 256 threads
// EPI: 0 = plain ; 2 = newton update C = 1.5*Pold - 0.5*acc
// ---------------------------------------------------------------------------
template<int EPI>
__global__ void __launch_bounds__(256)
sgemm64(const float* __restrict__ A, const float* __restrict__ B,
        float* __restrict__ C, const float* __restrict__ Pold)
{
    __shared__ float As[16][64];
    __shared__ float Bs[16][64];

    const int tid = threadIdx.x;
    const int brow = blockIdx.y * 64;
    const int bcol = blockIdx.x * 64;

    const int a_row = tid >> 2;          // 64 rows
    const int a_col = (tid & 3) * 4;     // 16 k-cols via float4
    const int b_row = tid >> 4;          // 16 k-rows
    const int b_col = (tid & 15) * 4;    // 64 n-cols via float4

    const int trow = (tid >> 4) * 4;
    const int tcol = (tid & 15) * 4;

    float acc[4][4] = {};

    for (int k0 = 0; k0 < DD; k0 += 16) {
        float4 av = *(const float4*)&A[(size_t)(brow + a_row) * DD + k0 + a_col];
        As[a_col + 0][a_row] = av.x;
        As[a_col + 1][a_row] = av.y;
        As[a_col + 2][a_row] = av.z;
        As[a_col + 3][a_row] = av.w;
        *(float4*)&Bs[b_row][b_col] =
            *(const float4*)&B[(size_t)(k0 + b_row) * DD + bcol + b_col];
        __syncthreads();

#pragma unroll
        for (int kk = 0; kk < 16; kk++) {
            float4 a0 = *(const float4*)&As[kk][trow];
            float4 b0 = *(const float4*)&Bs[kk][tcol];
            float ar[4] = {a0.x, a0.y, a0.z, a0.w};
            float br[4] = {b0.x, b0.y, b0.z, b0.w};
#pragma unroll
            for (int i = 0; i < 4; i++)
#pragma unroll
                for (int j = 0; j < 4; j++)
                    acc[i][j] = fmaf(ar[i], br[j], acc[i][j]);
        }
        __syncthreads();
    }

#pragma unroll
    for (int i = 0; i < 4; i++) {
        const size_t row = (size_t)(brow + trow + i);
#pragma unroll
        for (int j = 0; j < 4; j++) {
            const size_t idx = row * DD + bcol + tcol + j;
            if (EPI == 2)
                C[idx] = 1.5f * Pold[idx] - 0.5f * acc[i][j];
            else
                C[idx] = acc[i][j];
        }
    }
}

// ---------------------------------------------------------------------------
// Mean / trace / S / identity helpers
// ---------------------------------------------------------------------------
__global__ void colsum_partial(const float* __restrict__ H, float* __restrict__ colp)
{
    const int col = blockIdx.x * 128 + threadIdx.x;
    const int r0 = blockIdx.y * 512;
    float s = 0.0f;
    for (int r = 0; r < 512; r++)
        s += H[(size_t)(r0 + r) * DD + col];
    colp[blockIdx.y * DD + col] = s;
}

__global__ void mean_finalize(const float* __restrict__ colp, float* __restrict__ mean)
{
    const int i = threadIdx.x;
    float s = 0.0f;
    for (int c = 0; c < 128; c++)
        s += colp[c * DD + i];
    mean[i] = s * (1.0f / (float)NROWS);
}

__global__ void trace_kernel(const float* __restrict__ G,
                             const float* __restrict__ mean,
                             float* __restrict__ scalars)
{
    __shared__ float sm[512];
    const int i = threadIdx.x;
    const float m = mean[i];
    sm[i] = G[i * DD + i] * (1.0f / (float)NROWS) - m * m + INV_TEMP;
    __syncthreads();
    for (int s = 256; s > 0; s >>= 1) {
        if (i < s) sm[i] += sm[i + s];
        __syncthreads();
    }
    if (i == 0) {
        const float tr = sm[0];
        scalars[0] = tr;
        scalars[1] = 1.0f / tr;
        scalars[2] = rsqrtf(tr);
    }
}

__global__ void s_kernel(const float* __restrict__ G,
                         const float* __restrict__ mean,
                         const float* __restrict__ scalars,
                         float* __restrict__ S)
{
    const int i = blockIdx.x, j = threadIdx.x;
    const float invtr = scalars[1];
    float v = G[i * DD + j] * (1.0f / (float)NROWS) - mean[i] * mean[j];
    if (i == j) v += INV_TEMP;
    S[i * DD + j] = v * invtr;
}

__global__ void eye_kernel(float* __restrict__ P)
{
    const int i = blockIdx.x, j = threadIdx.x;
    P[i * DD + j] = (i == j) ? 1.0f : 0.0f;
}

// ---------------------------------------------------------------------------
// Host orchestration (graph-capturable: kernel launches only)
// ---------------------------------------------------------------------------
static void run_layer(const float* in, const float* W, float* out)
{
    float *H, *covp, *G, *S, *P, *Pn, *T1, *T2, *colp, *mean, *scal;
    cudaGetSymbolAddress((void**)&H,    g_H);
    cudaGetSymbolAddress((void**)&covp, g_covp);
    cudaGetSymbolAddress((void**)&G,    g_G);
    cudaGetSymbolAddress((void**)&S,    g_S);
    cudaGetSymbolAddress((void**)&P,    g_P);
    cudaGetSymbolAddress((void**)&Pn,   g_Pn);
    cudaGetSymbolAddress((void**)&T1,   g_T1);
    cudaGetSymbolAddress((void**)&T2,   g_T2);
    cudaGetSymbolAddress((void**)&colp, g_colp);
    cudaGetSymbolAddress((void**)&mean, g_mean);
    cudaGetSymbolAddress((void**)&scal, g_scalars);

    const dim3 gbig(DD / 128, NROWS / 128);   // (4, 512)

    // H = in @ W
    sgemm128<0, 0><<<gbig, 256>>>(in, W, H, DD, nullptr, nullptr);

    // column means of H
    colsum_partial<<<dim3(4, 128), 128>>>(H, colp);
    mean_finalize<<<1, 512>>>(colp, mean);

    // G = H^T H (deterministic split-K), then S = (G/n - m m^T + I/temp)/tr
    covgemm<<<dim3(4, 4, KSPLIT), 256>>>(H, covp);
    reduce_cov<<<512, 512>>>(covp, G);
    trace_kernel<<<1, 512>>>(G, mean, scal);
    s_kernel<<<512, 512>>>(G, mean, scal, S);

    // Newton-Schulz: P <- 1.5P - 0.5 (P@P)@(P@S)
    eye_kernel<<<512, 512>>>(P);
    float* Pa = P;
    float* Pb = Pn;
    for (int t = 0; t < NS_ITERS; t++) {
        sgemm64<0><<<dim3(8, 8), 256>>>(Pa, S,  T1, nullptr);   // T1 = P @ S
        sgemm64<0><<<dim3(8, 8), 256>>>(Pa, Pa, T2, nullptr);   // T2 = P @ P
        sgemm64<2><<<dim3(8, 8), 256>>>(T2, T1, Pb, Pa);        // Pb = 1.5P - 0.5 T2@T1
        float* tmp = Pa; Pa = Pb; Pb = tmp;
    }

    // out = (H - mean) @ (P * rsqrt(tr))
    sgemm128<1, 1><<<gbig, 256>>>(H, Pa, out, DD, mean, scal);
}

extern "C" void kernel_launch(void* const* d_in, const int* in_sizes, int n_in,
                              void* d_out, int out_size)
{
    (void)in_sizes; (void)n_in; (void)out_size;
    const float* x  = (const float*)d_in[0];
    const float* W0 = (const float*)d_in[1];
    const float* W1 = (const float*)d_in[2];
    const float* W2 = (const float*)d_in[3];
    float* out = (float*)d_out;

    float* o0 = out;
    float* o1 = out + (size_t)NROWS * DD;
    float* o2 = out + (size_t)2 * NROWS * DD;

    run_layer(x,  W0, o0);
    run_layer(o0, W1, o1);
    run_layer(o1, W2, o2);
}

// round 3
// speedup vs baseline: 1.8445x; 1.8445x over previous
#include <cuda_runtime.h>
#include <cuda_bf16.h>
#include <cstdint>
#include <math.h>

#define NROWS 65536
#define DD    512
#define KSPLIT 64
#define KCHUNK (NROWS / KSPLIT)   // 1024
#define NS_ITERS 10
#define INV_TEMP 0.1f

// ---------------------------------------------------------------------------
// Static device scratch (no allocations anywhere)
// ---------------------------------------------------------------------------
__device__ float g_H[(size_t)NROWS * DD];            // 128 MB
__device__ float g_covp[(size_t)KSPLIT * DD * DD];   // 64 MB
__device__ float g_G[DD * DD];
__device__ float g_S[DD * DD];
__device__ float g_P[DD * DD];
__device__ float g_Pn[DD * DD];
__device__ float g_T1[DD * DD];
__device__ float g_T2[DD * DD];
__device__ float g_colp[128 * DD];
__device__ float g_mean[DD];
__device__ float g_scalars[4];
__device__ __nv_bfloat16 g_Ah[(size_t)NROWS * DD];   // 64 MB A-operand hi
__device__ __nv_bfloat16 g_Al[(size_t)NROWS * DD];   // 64 MB A-operand lo
__device__ __nv_bfloat16 g_Wh[DD * DD];              // B-operand hi [k][n]
__device__ __nv_bfloat16 g_Wl[DD * DD];              // B-operand lo [k][n]

// ---------------------------------------------------------------------------
// PTX helpers
// ---------------------------------------------------------------------------
__device__ __forceinline__ uint32_t smem_u32(const void* p) {
    uint32_t a;
    asm("{ .reg .u64 t; cvta.to.shared.u64 t, %1; cvt.u32.u64 %0, t; }"
        : "=r"(a) : "l"(p));
    return a;
}
__device__ __forceinline__ void cpa16(uint32_t dst, const void* src) {
    asm volatile("cp.async.cg.shared.global [%0], [%1], 16;"
                 :: "r"(dst), "l"(src) : "memory");
}
#define CP_COMMIT() asm volatile("cp.async.commit_group;" ::: "memory")
#define CP_WAIT0()  asm volatile("cp.async.wait_group 0;" ::: "memory")

__device__ __forceinline__ void ldsm4(uint32_t* r, uint32_t a) {
    asm volatile("ldmatrix.sync.aligned.m8n8.x4.shared.b16 {%0,%1,%2,%3}, [%4];"
        : "=r"(r[0]), "=r"(r[1]), "=r"(r[2]), "=r"(r[3]) : "r"(a));
}
__device__ __forceinline__ void ldsm4t(uint32_t* r, uint32_t a) {
    asm volatile("ldmatrix.sync.aligned.m8n8.x4.trans.shared.b16 {%0,%1,%2,%3}, [%4];"
        : "=r"(r[0]), "=r"(r[1]), "=r"(r[2]), "=r"(r[3]) : "r"(a));
}
__device__ __forceinline__ void mma_bf16(float* d, const uint32_t* a, const uint32_t* b) {
    asm volatile("mma.sync.aligned.m16n8k16.row.col.f32.bf16.bf16.f32 "
        "{%0,%1,%2,%3}, {%4,%5,%6,%7}, {%8,%9}, {%0,%1,%2,%3};"
        : "+f"(d[0]), "+f"(d[1]), "+f"(d[2]), "+f"(d[3])
        : "r"(a[0]), "r"(a[1]), "r"(a[2]), "r"(a[3]), "r"(b[0]), "r"(b[1]));
}

// ---------------------------------------------------------------------------
// bf16 hi/lo split kernels (optional mean subtraction, row length 512)
// ---------------------------------------------------------------------------
__device__ __forceinline__ void split1(float v, __nv_bfloat16& h, __nv_bfloat16& l) {
    h = __float2bfloat16_rn(v);
    l = __float2bfloat16_rn(v - __bfloat162float(h));
}

template<int SUBMEAN>
__global__ void split_f32(const float* __restrict__ X,
                          __nv_bfloat16* __restrict__ Xh, __nv_bfloat16* __restrict__ Xl,
                          const float* __restrict__ mean)
{
    const size_t i = ((size_t)blockIdx.x * blockDim.x + threadIdx.x) * 4;
    float4 v = *(const float4*)(X + i);
    if (SUBMEAN) {
        const int c = (int)(i & (DD - 1));
        v.x -= mean[c + 0]; v.y -= mean[c + 1];
        v.z -= mean[c + 2]; v.w -= mean[c + 3];
    }
    __nv_bfloat16 h[4], l[4];
    split1(v.x, h[0], l[0]); split1(v.y, h[1], l[1]);
    split1(v.z, h[2], l[2]); split1(v.w, h[3], l[3]);
    *(uint64_t*)(Xh + i) = *(const uint64_t*)h;
    *(uint64_t*)(Xl + i) = *(const uint64_t*)l;
}

// ---------------------------------------------------------------------------
// Big GEMM via mma.sync: C[M,512] = A @ B (bf16 3-term emulation)
// CTA 128x128, k-chunk 32, 2-stage cp.async pipeline, 8 warps (2m x 4n)
// ---------------------------------------------------------------------------
#define LDA 80                      // A smem row bytes (32 bf16 + pad)
#define LDB 272                     // B smem row bytes (128 bf16 + pad)
#define A_TILE (128 * LDA)          // 10240
#define B_TILE (32 * LDB)           // 8704
#define G1_STAGE (2 * A_TILE + 2 * B_TILE)  // 37888
#define G1_SMEM (2 * G1_STAGE)              // 75776

template<int EPI>
__global__ void __launch_bounds__(256)
hgemm(const __nv_bfloat16* __restrict__ Ah, const __nv_bfloat16* __restrict__ Al,
      const __nv_bfloat16* __restrict__ Bh, const __nv_bfloat16* __restrict__ Bl,
      float* __restrict__ C, const float* __restrict__ scalars)
{
    extern __shared__ __align__(16) char smem[];
    const uint32_t sb = smem_u32(smem);
    const int tid = threadIdx.x;
    const int lane = tid & 31;
    const int wid = tid >> 5;
    const int m0 = blockIdx.y * 128;
    const int n0 = blockIdx.x * 128;
    const int wm = (wid & 1) * 64;
    const int wn = (wid >> 1) * 32;

    float acc[4][4][4] = {};

    auto loadStage = [&](int c, int s) {
        const uint32_t base = sb + s * G1_STAGE;
        const int k0 = c * 32;
#pragma unroll
        for (int rep = 0; rep < 4; rep++) {           // A tiles (h,l)
            const int idx = rep * 256 + tid;
            const int half = idx >> 9, r = (idx >> 2) & 127, ch = idx & 3;
            const __nv_bfloat16* src =
                (half ? Al : Ah) + (size_t)(m0 + r) * DD + k0 + ch * 8;
            cpa16(base + half * A_TILE + r * LDA + ch * 16, src);
        }
#pragma unroll
        for (int rep = 0; rep < 4; rep++) {           // B tiles (h,l)
            const int idx = rep * 256 + tid;
            const int half = idx >> 9, r = (idx >> 4) & 31, ch = idx & 15;
            const __nv_bfloat16* src =
                (half ? Bl : Bh) + (size_t)(k0 + r) * DD + n0 + ch * 8;
            cpa16(base + 2 * A_TILE + half * B_TILE + r * LDB + ch * 16, src);
        }
        CP_COMMIT();
    };

    loadStage(0, 0);

    for (int c = 0; c < DD / 32; c++) {
        CP_WAIT0();
        __syncthreads();
        if (c + 1 < DD / 32) loadStage(c + 1, (c + 1) & 1);
        const uint32_t st = sb + (c & 1) * G1_STAGE;

#pragma unroll
        for (int ks = 0; ks < 2; ks++) {
            // A fragments (row-major, no-trans)
            uint32_t ah[4][4], al[4][4];
            const uint32_t abase = st + (lane & 15) * LDA + ks * 32 + (lane >> 4) * 16;
#pragma unroll
            for (int mt = 0; mt < 4; mt++) {
                ldsm4(ah[mt], abase + (wm + mt * 16) * LDA);
                ldsm4(al[mt], abase + A_TILE + (wm + mt * 16) * LDA);
            }
            // B fragments (row-major [k][n], trans)
            const uint32_t brow = ks * 16 + (lane & 7) + ((lane >> 3) & 1) * 8;
            const uint32_t bbase = st + 2 * A_TILE + brow * LDB + wn * 2 + (lane >> 4) * 16;
            uint32_t bh[2][4], bl[2][4];
            ldsm4t(bh[0], bbase);
            ldsm4t(bh[1], bbase + 32);
            ldsm4t(bl[0], bbase + B_TILE);
            ldsm4t(bl[1], bbase + B_TILE + 32);

#pragma unroll
            for (int mt = 0; mt < 4; mt++)
#pragma unroll
                for (int nt = 0; nt < 4; nt++) {
                    const uint32_t* ph = &bh[nt >> 1][(nt & 1) * 2];
                    const uint32_t* pl = &bl[nt >> 1][(nt & 1) * 2];
                    mma_bf16(acc[mt][nt], ah[mt], ph);
                    mma_bf16(acc[mt][nt], ah[mt], pl);
                    mma_bf16(acc[mt][nt], al[mt], ph);
                }
        }
    }

    const float scale = EPI ? scalars[2] : 1.0f;
    const int g = lane >> 2, t4 = lane & 3;
#pragma unroll
    for (int mt = 0; mt < 4; mt++) {
        const int r0 = m0 + wm + mt * 16 + g;
#pragma unroll
        for (int nt = 0; nt < 4; nt++) {
            const int cc = n0 + wn + nt * 8 + 2 * t4;
            float2 v0 = {acc[mt][nt][0] * scale, acc[mt][nt][1] * scale};
            float2 v1 = {acc[mt][nt][2] * scale, acc[mt][nt][3] * scale};
            *(float2*)&C[(size_t)r0 * DD + cc] = v0;
            *(float2*)&C[(size_t)(r0 + 8) * DD + cc] = v1;
        }
    }
}

// ---------------------------------------------------------------------------
// Covariance split-K via mma.sync: Cp[z] = Hc^T Hc over chunk z (1024 rows)
// Both operands from H-split [n][d]; A-side uses trans ldmatrix (col-major A)
// ---------------------------------------------------------------------------
#define CV_STAGE (4 * B_TILE)       // 34816
#define CV_SMEM (2 * CV_STAGE)      // 69632

__global__ void __launch_bounds__(256)
hcov(const __nv_bfloat16* __restrict__ Hh, const __nv_bfloat16* __restrict__ Hl,
     float* __restrict__ Cp)
{
    extern __shared__ __align__(16) char smem[];
    const uint32_t sb = smem_u32(smem);
    const int tid = threadIdx.x;
    const int lane = tid & 31;
    const int wid = tid >> 5;
    const int i0 = blockIdx.y * 128;
    const int j0 = blockIdx.x * 128;
    const int z  = blockIdx.z;
    const int wm = (wid & 1) * 64;
    const int wn = (wid >> 1) * 32;

    float acc[4][4][4] = {};

    auto loadStage = [&](int c, int s) {
        const uint32_t base = sb + s * CV_STAGE;
        const int nbase = z * KCHUNK + c * 32;
#pragma unroll
        for (int rep = 0; rep < 8; rep++) {
            const int idx = rep * 256 + tid;           // 0..2047
            const int tile = idx >> 9;                 // 0:Ah 1:Al 2:Bh 3:Bl
            const int r = (idx >> 4) & 31, ch = idx & 15;
            const __nv_bfloat16* basep = (tile & 1) ? Hl : Hh;
            const int coff = (tile < 2) ? i0 : j0;
            const __nv_bfloat16* src = basep + (size_t)(nbase + r) * DD + coff + ch * 8;
            cpa16(base + tile * B_TILE + r * LDB + ch * 16, src);
        }
        CP_COMMIT();
    };

    loadStage(0, 0);

    for (int c = 0; c < KCHUNK / 32; c++) {
        CP_WAIT0();
        __syncthreads();
        if (c + 1 < KCHUNK / 32) loadStage(c + 1, (c + 1) & 1);
        const uint32_t st = sb + (c & 1) * CV_STAGE;

#pragma unroll
        for (int ks = 0; ks < 2; ks++) {
            // A-side: column-major A (storage [k=n][m=i]) -> trans ldmatrix
            const uint32_t arow = ks * 16 + (lane & 7) + ((lane >> 4) & 1) * 8;
            const uint32_t abase = st + arow * LDB + wm * 2 + ((lane >> 3) & 1) * 16;
            uint32_t ah[4][4], al[4][4];
#pragma unroll
            for (int mt = 0; mt < 4; mt++) {
                ldsm4t(ah[mt], abase + mt * 32);
                ldsm4t(al[mt], abase + B_TILE + mt * 32);
            }
            // B-side: row-major [k=n][n=j] -> trans ldmatrix
            const uint32_t brow = ks * 16 + (lane & 7) + ((lane >> 3) & 1) * 8;
            const uint32_t bbase = st + 2 * B_TILE + brow * LDB + wn * 2 + (lane >> 4) * 16;
            uint32_t bh[2][4], bl[2][4];
            ldsm4t(bh[0], bbase);
            ldsm4t(bh[1], bbase + 32);
            ldsm4t(bl[0], bbase + B_TILE);
            ldsm4t(bl[1], bbase + B_TILE + 32);

#pragma unroll
            for (int mt = 0; mt < 4; mt++)
#pragma unroll
                for (int nt = 0; nt < 4; nt++) {
                    const uint32_t* ph = &bh[nt >> 1][(nt & 1) * 2];
                    const uint32_t* pl = &bl[nt >> 1][(nt & 1) * 2];
                    mma_bf16(acc[mt][nt], ah[mt], ph);
                    mma_bf16(acc[mt][nt], ah[mt], pl);
                    mma_bf16(acc[mt][nt], al[mt], ph);
                }
        }
    }

    float* out = Cp + (size_t)z * DD * DD;
    const int g = lane >> 2, t4 = lane & 3;
#pragma unroll
    for (int mt = 0; mt < 4; mt++) {
        const int r0 = i0 + wm + mt * 16 + g;
#pragma unroll
        for (int nt = 0; nt < 4; nt++) {
            const int cc = j0 + wn + nt * 8 + 2 * t4;
            float2 v0 = {acc[mt][nt][0], acc[mt][nt][1]};
            float2 v1 = {acc[mt][nt][2], acc[mt][nt][3]};
            *(float2*)&out[(size_t)r0 * DD + cc] = v0;
            *(float2*)&out[(size_t)(r0 + 8) * DD + cc] = v1;
        }
    }
}

// ---------------------------------------------------------------------------
// Deterministic split-K reduction
// ---------------------------------------------------------------------------
__global__ void reduce_cov(const float* __restrict__ Cp, float* __restrict__ G)
{
    const int idx = blockIdx.x * 512 + threadIdx.x;
    float s = 0.0f;
#pragma unroll 8
    for (int zz = 0; zz < KSPLIT; zz++)
        s += Cp[(size_t)zz * DD * DD + idx];
    G[idx] = s;
}

// ---------------------------------------------------------------------------
// Small FFMA GEMM for Newton-Schulz
// ---------------------------------------------------------------------------
template<int EPI>
__global__ void __launch_bounds__(256)
sgemm64(const float* __restrict__ A, const float* __restrict__ B,
        float* __restrict__ C, const float* __restrict__ Pold)
{
    __shared__ float As[16][64];
    __shared__ float Bs[16][64];

    const int tid = threadIdx.x;
    const int brow = blockIdx.y * 64;
    const int bcol = blockIdx.x * 64;

    const int a_row = tid >> 2;
    const int a_col = (tid & 3) * 4;
    const int b_row = tid >> 4;
    const int b_col = (tid & 15) * 4;
    const int trow = (tid >> 4) * 4;
    const int tcol = (tid & 15) * 4;

    float acc[4][4] = {};

    for (int k0 = 0; k0 < DD; k0 += 16) {
        float4 av = *(const float4*)&A[(size_t)(brow + a_row) * DD + k0 + a_col];
        As[a_col + 0][a_row] = av.x;
        As[a_col + 1][a_row] = av.y;
        As[a_col + 2][a_row] = av.z;
        As[a_col + 3][a_row] = av.w;
        *(float4*)&Bs[b_row][b_col] =
            *(const float4*)&B[(size_t)(k0 + b_row) * DD + bcol + b_col];
        __syncthreads();

#pragma unroll
        for (int kk = 0; kk < 16; kk++) {
            float4 a0 = *(const float4*)&As[kk][trow];
            float4 b0 = *(const float4*)&Bs[kk][tcol];
            float ar[4] = {a0.x, a0.y, a0.z, a0.w};
            float br[4] = {b0.x, b0.y, b0.z, b0.w};
#pragma unroll
            for (int i = 0; i < 4; i++)
#pragma unroll
                for (int j = 0; j < 4; j++)
                    acc[i][j] = fmaf(ar[i], br[j], acc[i][j]);
        }
        __syncthreads();
    }

#pragma unroll
    for (int i = 0; i < 4; i++) {
        const size_t row = (size_t)(brow + trow + i);
#pragma unroll
        for (int j = 0; j < 4; j++) {
            const size_t idx = row * DD + bcol + tcol + j;
            if (EPI == 2)
                C[idx] = 1.5f * Pold[idx] - 0.5f * acc[i][j];
            else
                C[idx] = acc[i][j];
        }
    }
}

// ---------------------------------------------------------------------------
// Mean / trace / S / identity helpers
// ---------------------------------------------------------------------------
__global__ void colsum_partial(const float* __restrict__ H, float* __restrict__ colp)
{
    const int col = blockIdx.x * 128 + threadIdx.x;
    const int r0 = blockIdx.y * 512;
    float s = 0.0f;
    for (int r = 0; r < 512; r++)
        s += H[(size_t)(r0 + r) * DD + col];
    colp[blockIdx.y * DD + col] = s;
}

__global__ void mean_finalize(const float* __restrict__ colp, float* __restrict__ mean)
{
    const int i = threadIdx.x;
    float s = 0.0f;
    for (int c = 0; c < 128; c++)
        s += colp[c * DD + i];
    mean[i] = s * (1.0f / (float)NROWS);
}

__global__ void trace_kernel(const float* __restrict__ G,
                             const float* __restrict__ mean,
                             float* __restrict__ scalars)
{
    __shared__ float sm[512];
    const int i = threadIdx.x;
    const float m = mean[i];
    sm[i] = G[i * DD + i] * (1.0f / (float)NROWS) - m * m + INV_TEMP;
    __syncthreads();
    for (int s = 256; s > 0; s >>= 1) {
        if (i < s) sm[i] += sm[i + s];
        __syncthreads();
    }
    if (i == 0) {
        const float tr = sm[0];
        scalars[0] = tr;
        scalars[1] = 1.0f / tr;
        scalars[2] = rsqrtf(tr);
    }
}

__global__ void s_kernel(const float* __restrict__ G,
                         const float* __restrict__ mean,
                         const float* __restrict__ scalars,
                         float* __restrict__ S)
{
    const int i = blockIdx.x, j = threadIdx.x;
    const float invtr = scalars[1];
    float v = G[i * DD + j] * (1.0f / (float)NROWS) - mean[i] * mean[j];
    if (i == j) v += INV_TEMP;
    S[i * DD + j] = v * invtr;
}

__global__ void eye_kernel(float* __restrict__ P)
{
    const int i = blockIdx.x, j = threadIdx.x;
    P[i * DD + j] = (i == j) ? 1.0f : 0.0f;
}

// ---------------------------------------------------------------------------
// Host orchestration (kernel launches only; graph-capturable)
// ---------------------------------------------------------------------------
static void run_layer(const float* in, const float* W, float* out)
{
    float *H, *covp, *G, *S, *P, *Pn, *T1, *T2, *colp, *mean, *scal;
    __nv_bfloat16 *Ah, *Al, *Wh, *Wl;
    cudaGetSymbolAddress((void**)&H,    g_H);
    cudaGetSymbolAddress((void**)&covp, g_covp);
    cudaGetSymbolAddress((void**)&G,    g_G);
    cudaGetSymbolAddress((void**)&S,    g_S);
    cudaGetSymbolAddress((void**)&P,    g_P);
    cudaGetSymbolAddress((void**)&Pn,   g_Pn);
    cudaGetSymbolAddress((void**)&T1,   g_T1);
    cudaGetSymbolAddress((void**)&T2,   g_T2);
    cudaGetSymbolAddress((void**)&colp, g_colp);
    cudaGetSymbolAddress((void**)&mean, g_mean);
    cudaGetSymbolAddress((void**)&scal, g_scalars);
    cudaGetSymbolAddress((void**)&Ah,   g_Ah);
    cudaGetSymbolAddress((void**)&Al,   g_Al);
    cudaGetSymbolAddress((void**)&Wh,   g_Wh);
    cudaGetSymbolAddress((void**)&Wl,   g_Wl);

    const int bigBlocks = (NROWS * DD) / (256 * 4);   // 32768
    const int wBlocks   = (DD * DD) / (256 * 4);      // 256

    // H = in @ W
    split_f32<0><<<wBlocks, 256>>>(W, Wh, Wl, nullptr);
    split_f32<0><<<bigBlocks, 256>>>(in, Ah, Al, nullptr);
    hgemm<0><<<dim3(4, 512), 256, G1_SMEM>>>(Ah, Al, Wh, Wl, H, scal);

    // mean
    colsum_partial<<<dim3(4, 128), 128>>>(H, colp);
    mean_finalize<<<1, 512>>>(colp, mean);

    // cov: split H, G = H^T H (split-K), S
    split_f32<0><<<bigBlocks, 256>>>(H, Ah, Al, nullptr);
    hcov<<<dim3(4, 4, KSPLIT), 256, CV_SMEM>>>(Ah, Al, covp);
    reduce_cov<<<512, 512>>>(covp, G);
    trace_kernel<<<1, 512>>>(G, mean, scal);
    s_kernel<<<512, 512>>>(G, mean, scal, S);

    // Newton-Schulz
    eye_kernel<<<512, 512>>>(P);
    float* Pa = P;
    float* Pb = Pn;
    for (int t = 0; t < NS_ITERS; t++) {
        sgemm64<0><<<dim3(8, 8), 256>>>(Pa, S,  T1, nullptr);
        sgemm64<0><<<dim3(8, 8), 256>>>(Pa, Pa, T2, nullptr);
        sgemm64<2><<<dim3(8, 8), 256>>>(T2, T1, Pb, Pa);
        float* tmp = Pa; Pa = Pb; Pb = tmp;
    }

    // out = (H - mean) @ Pa * rsqrt(tr)
    split_f32<0><<<wBlocks, 256>>>(Pa, Wh, Wl, nullptr);
    split_f32<1><<<bigBlocks, 256>>>(H, Ah, Al, mean);
    hgemm<1><<<dim3(4, 512), 256, G1_SMEM>>>(Ah, Al, Wh, Wl, out, scal);
}

extern "C" void kernel_launch(void* const* d_in, const int* in_sizes, int n_in,
                              void* d_out, int out_size)
{
    (void)in_sizes; (void)n_in; (void)out_size;
    const float* x  = (const float*)d_in[0];
    const float* W0 = (const float*)d_in[1];
    const float* W1 = (const float*)d_in[2];
    const float* W2 = (const float*)d_in[3];
    float* out = (float*)d_out;

    cudaFuncSetAttribute(hgemm<0>, cudaFuncAttributeMaxDynamicSharedMemorySize, G1_SMEM);
    cudaFuncSetAttribute(hgemm<1>, cudaFuncAttributeMaxDynamicSharedMemorySize, G1_SMEM);
    cudaFuncSetAttribute(hcov,     cudaFuncAttributeMaxDynamicSharedMemorySize, CV_SMEM);

    float* o0 = out;
    float* o1 = out + (size_t)NROWS * DD;
    float* o2 = out + (size_t)2 * NROWS * DD;

    run_layer(x,  W0, o0);
    run_layer(o0, W1, o1);
    run_layer(o1, W2, o2);
}

// round 4
// speedup vs baseline: 3.0201x; 1.6373x over previous
#include <cuda_runtime.h>
#include <cuda_bf16.h>
#include <cstdint>
#include <math.h>

#define NROWS 65536
#define DD    512
#define KSPLIT 64
#define KCHUNK (NROWS / KSPLIT)   // 1024
#define NS_ITERS 10
#define INV_TEMP 0.1f

// ---------------------------------------------------------------------------
// Static device scratch
// ---------------------------------------------------------------------------
__device__ float g_covp[(size_t)KSPLIT * DD * DD];   // 64 MB
__device__ float g_G[DD * DD];
__device__ float g_S[DD * DD];
__device__ float g_P[DD * DD];
__device__ float g_Pn[DD * DD];
__device__ float g_colp[128 * DD];
__device__ float g_mean[DD];
__device__ float g_mc[DD];
__device__ float g_scalars[4];
__device__ __nv_bfloat16 g_Ah[(size_t)NROWS * DD];   // input splits (layer chain)
__device__ __nv_bfloat16 g_Al[(size_t)NROWS * DD];
__device__ __nv_bfloat16 g_Hh[(size_t)NROWS * DD];   // H splits
__device__ __nv_bfloat16 g_Hl[(size_t)NROWS * DD];
__device__ __nv_bfloat16 g_Wh[DD * DD];
__device__ __nv_bfloat16 g_Wl[DD * DD];
__device__ __nv_bfloat16 g_Sh[DD * DD], g_Sl[DD * DD];
__device__ __nv_bfloat16 g_Pah[DD * DD], g_Pal[DD * DD];
__device__ __nv_bfloat16 g_Pbh[DD * DD], g_Pbl[DD * DD];
__device__ __nv_bfloat16 g_T1h[DD * DD], g_T1l[DD * DD];
__device__ __nv_bfloat16 g_T2h[DD * DD], g_T2l[DD * DD];

// ---------------------------------------------------------------------------
// PTX helpers
// ---------------------------------------------------------------------------
__device__ __forceinline__ uint32_t smem_u32(const void* p) {
    uint32_t a;
    asm("{ .reg .u64 t; cvta.to.shared.u64 t, %1; cvt.u32.u64 %0, t; }"
        : "=r"(a) : "l"(p));
    return a;
}
__device__ __forceinline__ void cpa16(uint32_t dst, const void* src) {
    asm volatile("cp.async.cg.shared.global [%0], [%1], 16;"
                 :: "r"(dst), "l"(src) : "memory");
}
#define CP_COMMIT() asm volatile("cp.async.commit_group;" ::: "memory")
#define CP_WAIT0()  asm volatile("cp.async.wait_group 0;" ::: "memory")

__device__ __forceinline__ void ldsm4(uint32_t* r, uint32_t a) {
    asm volatile("ldmatrix.sync.aligned.m8n8.x4.shared.b16 {%0,%1,%2,%3}, [%4];"
        : "=r"(r[0]), "=r"(r[1]), "=r"(r[2]), "=r"(r[3]) : "r"(a));
}
__device__ __forceinline__ void ldsm4t(uint32_t* r, uint32_t a) {
    asm volatile("ldmatrix.sync.aligned.m8n8.x4.trans.shared.b16 {%0,%1,%2,%3}, [%4];"
        : "=r"(r[0]), "=r"(r[1]), "=r"(r[2]), "=r"(r[3]) : "r"(a));
}
__device__ __forceinline__ void mma_bf16(float* d, const uint32_t* a, const uint32_t* b) {
    asm volatile("mma.sync.aligned.m16n8k16.row.col.f32.bf16.bf16.f32 "
        "{%0,%1,%2,%3}, {%4,%5,%6,%7}, {%8,%9}, {%0,%1,%2,%3};"
        : "+f"(d[0]), "+f"(d[1]), "+f"(d[2]), "+f"(d[3])
        : "r"(a[0]), "r"(a[1]), "r"(a[2]), "r"(a[3]), "r"(b[0]), "r"(b[1]));
}

__device__ __forceinline__ void split1(float v, __nv_bfloat16& h, __nv_bfloat16& l) {
    h = __float2bfloat16_rn(v);
    l = __float2bfloat16_rn(v - __bfloat162float(h));
}
// write a float pair as packed hi/lo bf16x2 at element offset (even)
__device__ __forceinline__ void store_split2(__nv_bfloat16* Xh, __nv_bfloat16* Xl,
                                             size_t off, float a, float b) {
    __nv_bfloat16 ha, la, hb, lb;
    split1(a, ha, la);
    split1(b, hb, lb);
    *(uint32_t*)(Xh + off) =
        ((uint32_t)__bfloat16_as_ushort(hb) << 16) | __bfloat16_as_ushort(ha);
    *(uint32_t*)(Xl + off) =
        ((uint32_t)__bfloat16_as_ushort(lb) << 16) | __bfloat16_as_ushort(la);
}

template<int SUBMEAN>
__global__ void split_f32(const float* __restrict__ X,
                          __nv_bfloat16* __restrict__ Xh, __nv_bfloat16* __restrict__ Xl,
                          const float* __restrict__ mean)
{
    const size_t i = ((size_t)blockIdx.x * blockDim.x + threadIdx.x) * 4;
    float4 v = *(const float4*)(X + i);
    if (SUBMEAN) {
        const int c = (int)(i & (DD - 1));
        v.x -= mean[c + 0]; v.y -= mean[c + 1];
        v.z -= mean[c + 2]; v.w -= mean[c + 3];
    }
    __nv_bfloat16 h[4], l[4];
    split1(v.x, h[0], l[0]); split1(v.y, h[1], l[1]);
    split1(v.z, h[2], l[2]); split1(v.w, h[3], l[3]);
    *(uint64_t*)(Xh + i) = *(const uint64_t*)h;
    *(uint64_t*)(Xl + i) = *(const uint64_t*)l;
}

// ---------------------------------------------------------------------------
// Big GEMM via mma.sync: C[M,512] = A @ B (bf16 3-term emulation)
// MODE 0: write split(acc) to Ch/Cl only.
// MODE 1: write fp32 acc*s2 - mc[col] to Cf32 AND split of it to Ch/Cl.
// ---------------------------------------------------------------------------
#define LDA 80
#define LDB 272
#define A_TILE (128 * LDA)
#define B_TILE (32 * LDB)
#define G1_STAGE (2 * A_TILE + 2 * B_TILE)
#define G1_SMEM (2 * G1_STAGE)

template<int MODE>
__global__ void __launch_bounds__(256)
hgemm(const __nv_bfloat16* __restrict__ Ah, const __nv_bfloat16* __restrict__ Al,
      const __nv_bfloat16* __restrict__ Bh, const __nv_bfloat16* __restrict__ Bl,
      float* __restrict__ Cf32,
      __nv_bfloat16* __restrict__ Ch, __nv_bfloat16* __restrict__ Cl,
      const float* __restrict__ scalars, const float* __restrict__ mc)
{
    extern __shared__ __align__(16) char smem[];
    const uint32_t sb = smem_u32(smem);
    const int tid = threadIdx.x;
    const int lane = tid & 31;
    const int wid = tid >> 5;
    const int m0 = blockIdx.y * 128;
    const int n0 = blockIdx.x * 128;
    const int wm = (wid & 1) * 64;
    const int wn = (wid >> 1) * 32;

    float acc[4][4][4] = {};

    auto loadStage = [&](int c, int s) {
        const uint32_t base = sb + s * G1_STAGE;
        const int k0 = c * 32;
#pragma unroll
        for (int rep = 0; rep < 4; rep++) {
            const int idx = rep * 256 + tid;
            const int half = idx >> 9, r = (idx >> 2) & 127, ch = idx & 3;
            const __nv_bfloat16* src =
                (half ? Al : Ah) + (size_t)(m0 + r) * DD + k0 + ch * 8;
            cpa16(base + half * A_TILE + r * LDA + ch * 16, src);
        }
#pragma unroll
        for (int rep = 0; rep < 4; rep++) {
            const int idx = rep * 256 + tid;
            const int half = idx >> 9, r = (idx >> 4) & 31, ch = idx & 15;
            const __nv_bfloat16* src =
                (half ? Bl : Bh) + (size_t)(k0 + r) * DD + n0 + ch * 8;
            cpa16(base + 2 * A_TILE + half * B_TILE + r * LDB + ch * 16, src);
        }
        CP_COMMIT();
    };

    loadStage(0, 0);

    for (int c = 0; c < DD / 32; c++) {
        CP_WAIT0();
        __syncthreads();
        if (c + 1 < DD / 32) loadStage(c + 1, (c + 1) & 1);
        const uint32_t st = sb + (c & 1) * G1_STAGE;

#pragma unroll
        for (int ks = 0; ks < 2; ks++) {
            uint32_t ah[4][4], al[4][4];
            const uint32_t abase = st + (lane & 15) * LDA + ks * 32 + (lane >> 4) * 16;
#pragma unroll
            for (int mt = 0; mt < 4; mt++) {
                ldsm4(ah[mt], abase + (wm + mt * 16) * LDA);
                ldsm4(al[mt], abase + A_TILE + (wm + mt * 16) * LDA);
            }
            const uint32_t brow = ks * 16 + (lane & 7) + ((lane >> 3) & 1) * 8;
            const uint32_t bbase = st + 2 * A_TILE + brow * LDB + wn * 2 + (lane >> 4) * 16;
            uint32_t bh[2][4], bl[2][4];
            ldsm4t(bh[0], bbase);
            ldsm4t(bh[1], bbase + 32);
            ldsm4t(bl[0], bbase + B_TILE);
            ldsm4t(bl[1], bbase + B_TILE + 32);

#pragma unroll
            for (int mt = 0; mt < 4; mt++)
#pragma unroll
                for (int nt = 0; nt < 4; nt++) {
                    const uint32_t* ph = &bh[nt >> 1][(nt & 1) * 2];
                    const uint32_t* pl = &bl[nt >> 1][(nt & 1) * 2];
                    mma_bf16(acc[mt][nt], ah[mt], ph);
                    mma_bf16(acc[mt][nt], ah[mt], pl);
                    mma_bf16(acc[mt][nt], al[mt], ph);
                }
        }
    }

    const float s2 = (MODE == 1) ? scalars[2] : 1.0f;
    const int g = lane >> 2, t4 = lane & 3;
#pragma unroll
    for (int mt = 0; mt < 4; mt++) {
        const int r0 = m0 + wm + mt * 16 + g;
#pragma unroll
        for (int nt = 0; nt < 4; nt++) {
            const int cc = n0 + wn + nt * 8 + 2 * t4;
            float v0 = acc[mt][nt][0], v1 = acc[mt][nt][1];
            float v2 = acc[mt][nt][2], v3 = acc[mt][nt][3];
            if (MODE == 1) {
                const float2 m2 = *(const float2*)&mc[cc];
                v0 = v0 * s2 - m2.x; v1 = v1 * s2 - m2.y;
                v2 = v2 * s2 - m2.x; v3 = v3 * s2 - m2.y;
                *(float2*)&Cf32[(size_t)r0 * DD + cc] = make_float2(v0, v1);
                *(float2*)&Cf32[(size_t)(r0 + 8) * DD + cc] = make_float2(v2, v3);
            }
            store_split2(Ch, Cl, (size_t)r0 * DD + cc, v0, v1);
            store_split2(Ch, Cl, (size_t)(r0 + 8) * DD + cc, v2, v3);
        }
    }
}

// ---------------------------------------------------------------------------
// Covariance split-K (upper-triangle tiles only): Cp[z] = Hc^T Hc
// ---------------------------------------------------------------------------
#define CV_STAGE (4 * B_TILE)
#define CV_SMEM (2 * CV_STAGE)

__global__ void __launch_bounds__(256)
hcov(const __nv_bfloat16* __restrict__ Hh, const __nv_bfloat16* __restrict__ Hl,
     float* __restrict__ Cp)
{
    extern __shared__ __align__(16) char smem[];
    const uint32_t sb = smem_u32(smem);
    const int tid = threadIdx.x;
    const int lane = tid & 31;
    const int wid = tid >> 5;
    const int bx = blockIdx.x;                 // 0..9 upper-triangle tile pairs
    const int bi = (bx < 4) ? 0 : (bx < 7) ? 1 : (bx < 9) ? 2 : 3;
    const int bj = bx - ((bi == 0) ? 0 : (bi == 1) ? 3 : (bi == 2) ? 5 : 6);
    const int i0 = bi * 128;
    const int j0 = bj * 128;
    const int z  = blockIdx.z;
    const int wm = (wid & 1) * 64;
    const int wn = (wid >> 1) * 32;

    float acc[4][4][4] = {};

    auto loadStage = [&](int c, int s) {
        const uint32_t base = sb + s * CV_STAGE;
        const int nbase = z * KCHUNK + c * 32;
#pragma unroll
        for (int rep = 0; rep < 8; rep++) {
            const int idx = rep * 256 + tid;
            const int tile = idx >> 9;
            const int r = (idx >> 4) & 31, ch = idx & 15;
            const __nv_bfloat16* basep = (tile & 1) ? Hl : Hh;
            const int coff = (tile < 2) ? i0 : j0;
            const __nv_bfloat16* src = basep + (size_t)(nbase + r) * DD + coff + ch * 8;
            cpa16(base + tile * B_TILE + r * LDB + ch * 16, src);
        }
        CP_COMMIT();
    };

    loadStage(0, 0);

    for (int c = 0; c < KCHUNK / 32; c++) {
        CP_WAIT0();
        __syncthreads();
        if (c + 1 < KCHUNK / 32) loadStage(c + 1, (c + 1) & 1);
        const uint32_t st = sb + (c & 1) * CV_STAGE;

#pragma unroll
        for (int ks = 0; ks < 2; ks++) {
            const uint32_t arow = ks * 16 + (lane & 7) + ((lane >> 4) & 1) * 8;
            const uint32_t abase = st + arow * LDB + wm * 2 + ((lane >> 3) & 1) * 16;
            uint32_t ah[4][4], al[4][4];
#pragma unroll
            for (int mt = 0; mt < 4; mt++) {
                ldsm4t(ah[mt], abase + mt * 32);
                ldsm4t(al[mt], abase + B_TILE + mt * 32);
            }
            const uint32_t brow = ks * 16 + (lane & 7) + ((lane >> 3) & 1) * 8;
            const uint32_t bbase = st + 2 * B_TILE + brow * LDB + wn * 2 + (lane >> 4) * 16;
            uint32_t bh[2][4], bl[2][4];
            ldsm4t(bh[0], bbase);
            ldsm4t(bh[1], bbase + 32);
            ldsm4t(bl[0], bbase + B_TILE);
            ldsm4t(bl[1], bbase + B_TILE + 32);

#pragma unroll
            for (int mt = 0; mt < 4; mt++)
#pragma unroll
                for (int nt = 0; nt < 4; nt++) {
                    const uint32_t* ph = &bh[nt >> 1][(nt & 1) * 2];
                    const uint32_t* pl = &bl[nt >> 1][(nt & 1) * 2];
                    mma_bf16(acc[mt][nt], ah[mt], ph);
                    mma_bf16(acc[mt][nt], ah[mt], pl);
                    mma_bf16(acc[mt][nt], al[mt], ph);
                }
        }
    }

    float* out = Cp + (size_t)z * DD * DD;
    const int g = lane >> 2, t4 = lane & 3;
#pragma unroll
    for (int mt = 0; mt < 4; mt++) {
        const int r0 = i0 + wm + mt * 16 + g;
#pragma unroll
        for (int nt = 0; nt < 4; nt++) {
            const int cc = j0 + wn + nt * 8 + 2 * t4;
            float2 v0 = {acc[mt][nt][0], acc[mt][nt][1]};
            float2 v1 = {acc[mt][nt][2], acc[mt][nt][3]};
            *(float2*)&out[(size_t)r0 * DD + cc] = v0;
            *(float2*)&out[(size_t)(r0 + 8) * DD + cc] = v1;
        }
    }
}

// Deterministic symmetric split-K reduction (upper triangle + mirror)
__global__ void reduce_cov_sym(const float* __restrict__ Cp, float* __restrict__ G)
{
    const int i = blockIdx.x, j = threadIdx.x;
    if (j < i) return;
    float s = 0.0f;
#pragma unroll 8
    for (int zz = 0; zz < KSPLIT; zz++)
        s += Cp[(size_t)zz * DD * DD + i * DD + j];
    G[i * DD + j] = s;
    G[j * DD + i] = s;
}

// ---------------------------------------------------------------------------
// Newton-Schulz small GEMMs on tensor cores (64x64 tiles, 4 warps)
// ---------------------------------------------------------------------------
#define NS_LDA 80
#define NS_AT  (64 * NS_LDA)      // 5120
#define NS_LDB 144
#define NS_BT  (32 * NS_LDB)      // 4608
#define NS_STAGE (2 * NS_AT + 2 * NS_BT)   // 19456
#define NS_SMEM  (2 * NS_STAGE)            // 38912

struct NsAcc { float a[2][4][4]; };

__device__ __forceinline__ void ns_core(
    const __nv_bfloat16* __restrict__ Ah, const __nv_bfloat16* __restrict__ Al,
    const __nv_bfloat16* __restrict__ Bh, const __nv_bfloat16* __restrict__ Bl,
    int m0, int n0, uint32_t sb, NsAcc& A)
{
    const int tid = threadIdx.x;
    const int lane = tid & 31;
    const int wid = tid >> 5;
    const int wm = (wid & 1) * 32;
    const int wn = (wid >> 1) * 32;

    auto loadStage = [&](int c, int s) {
        const uint32_t base = sb + s * NS_STAGE;
        const int k0 = c * 32;
#pragma unroll
        for (int rep = 0; rep < 8; rep++) {
            const int idx = rep * 128 + tid;
            if (idx < 512) {
                const int half = idx >> 8, r = (idx >> 2) & 63, ch = idx & 3;
                const __nv_bfloat16* src =
                    (half ? Al : Ah) + (size_t)(m0 + r) * DD + k0 + ch * 8;
                cpa16(base + half * NS_AT + r * NS_LDA + ch * 16, src);
            } else {
                const int j = idx - 512;
                const int half = j >> 8, r = (j >> 3) & 31, ch = j & 7;
                const __nv_bfloat16* src =
                    (half ? Bl : Bh) + (size_t)(k0 + r) * DD + n0 + ch * 8;
                cpa16(base + 2 * NS_AT + half * NS_BT + r * NS_LDB + ch * 16, src);
            }
        }
        CP_COMMIT();
    };

    loadStage(0, 0);

    for (int c = 0; c < DD / 32; c++) {
        CP_WAIT0();
        __syncthreads();
        if (c + 1 < DD / 32) loadStage(c + 1, (c + 1) & 1);
        const uint32_t st = sb + (c & 1) * NS_STAGE;

#pragma unroll
        for (int ks = 0; ks < 2; ks++) {
            uint32_t ah[2][4], al[2][4];
            const uint32_t abase = st + (lane & 15) * NS_LDA + ks * 32 + (lane >> 4) * 16;
#pragma unroll
            for (int mt = 0; mt < 2; mt++) {
                ldsm4(ah[mt], abase + (wm + mt * 16) * NS_LDA);
                ldsm4(al[mt], abase + NS_AT + (wm + mt * 16) * NS_LDA);
            }
            const uint32_t brow = ks * 16 + (lane & 7) + ((lane >> 3) & 1) * 8;
            const uint32_t bbase = st + 2 * NS_AT + brow * NS_LDB + wn * 2 + (lane >> 4) * 16;
            uint32_t bh[2][4], bl[2][4];
            ldsm4t(bh[0], bbase);
            ldsm4t(bh[1], bbase + 32);
            ldsm4t(bl[0], bbase + NS_BT);
            ldsm4t(bl[1], bbase + NS_BT + 32);

#pragma unroll
            for (int mt = 0; mt < 2; mt++)
#pragma unroll
                for (int nt = 0; nt < 4; nt++) {
                    const uint32_t* ph = &bh[nt >> 1][(nt & 1) * 2];
                    const uint32_t* pl = &bl[nt >> 1][(nt & 1) * 2];
                    mma_bf16(A.a[mt][nt], ah[mt], ph);
                    mma_bf16(A.a[mt][nt], ah[mt], pl);
                    mma_bf16(A.a[mt][nt], al[mt], ph);
                }
        }
    }
}

// grid (8,8,2): z=0 -> T1 = P @ S ; z=1 -> T2 = P @ P ; outputs as splits
__global__ void __launch_bounds__(128)
ns_pair(const __nv_bfloat16* __restrict__ Pah, const __nv_bfloat16* __restrict__ Pal,
        const __nv_bfloat16* __restrict__ Sh,  const __nv_bfloat16* __restrict__ Sl,
        __nv_bfloat16* __restrict__ T1h, __nv_bfloat16* __restrict__ T1l,
        __nv_bfloat16* __restrict__ T2h, __nv_bfloat16* __restrict__ T2l)
{
    __shared__ __align__(16) char smem[NS_SMEM];
    const uint32_t sb = smem_u32(smem);
    const int m0 = blockIdx.y * 64;
    const int n0 = blockIdx.x * 64;
    const int lane = threadIdx.x & 31;
    const int wid = threadIdx.x >> 5;
    const int wm = (wid & 1) * 32;
    const int wn = (wid >> 1) * 32;

    NsAcc A = {};
    const __nv_bfloat16* Bh = blockIdx.z ? Pah : Sh;
    const __nv_bfloat16* Bl = blockIdx.z ? Pal : Sl;
    ns_core(Pah, Pal, Bh, Bl, m0, n0, sb, A);

    __nv_bfloat16* Oh = blockIdx.z ? T2h : T1h;
    __nv_bfloat16* Ol = blockIdx.z ? T2l : T1l;
    const int g = lane >> 2, t4 = lane & 3;
#pragma unroll
    for (int mt = 0; mt < 2; mt++) {
        const int r0 = m0 + wm + mt * 16 + g;
#pragma unroll
        for (int nt = 0; nt < 4; nt++) {
            const int cc = n0 + wn + nt * 8 + 2 * t4;
            store_split2(Oh, Ol, (size_t)r0 * DD + cc, A.a[mt][nt][0], A.a[mt][nt][1]);
            store_split2(Oh, Ol, (size_t)(r0 + 8) * DD + cc, A.a[mt][nt][2], A.a[mt][nt][3]);
        }
    }
}

// grid (8,8): Pb = 1.5*Pold - 0.5*(T2 @ T1); writes fp32 + splits
__global__ void __launch_bounds__(128)
ns_update(const __nv_bfloat16* __restrict__ T2h, const __nv_bfloat16* __restrict__ T2l,
          const __nv_bfloat16* __restrict__ T1h, const __nv_bfloat16* __restrict__ T1l,
          const float* __restrict__ Pold, float* __restrict__ Pnew,
          __nv_bfloat16* __restrict__ Pnh, __nv_bfloat16* __restrict__ Pnl)
{
    __shared__ __align__(16) char smem[NS_SMEM];
    const uint32_t sb = smem_u32(smem);
    const int m0 = blockIdx.y * 64;
    const int n0 = blockIdx.x * 64;
    const int lane = threadIdx.x & 31;
    const int wid = threadIdx.x >> 5;
    const int wm = (wid & 1) * 32;
    const int wn = (wid >> 1) * 32;

    NsAcc A = {};
    ns_core(T2h, T2l, T1h, T1l, m0, n0, sb, A);

    const int g = lane >> 2, t4 = lane & 3;
#pragma unroll
    for (int mt = 0; mt < 2; mt++) {
        const int r0 = m0 + wm + mt * 16 + g;
#pragma unroll
        for (int nt = 0; nt < 4; nt++) {
            const int cc = n0 + wn + nt * 8 + 2 * t4;
            {
                const size_t idx = (size_t)r0 * DD + cc;
                const float2 po = *(const float2*)&Pold[idx];
                const float v0 = 1.5f * po.x - 0.5f * A.a[mt][nt][0];
                const float v1 = 1.5f * po.y - 0.5f * A.a[mt][nt][1];
                *(float2*)&Pnew[idx] = make_float2(v0, v1);
                store_split2(Pnh, Pnl, idx, v0, v1);
            }
            {
                const size_t idx = (size_t)(r0 + 8) * DD + cc;
                const float2 po = *(const float2*)&Pold[idx];
                const float v0 = 1.5f * po.x - 0.5f * A.a[mt][nt][2];
                const float v1 = 1.5f * po.y - 0.5f * A.a[mt][nt][3];
                *(float2*)&Pnew[idx] = make_float2(v0, v1);
                store_split2(Pnh, Pnl, idx, v0, v1);
            }
        }
    }
}

// ---------------------------------------------------------------------------
// Mean / trace / S / identity / mc helpers
// ---------------------------------------------------------------------------
__global__ void colsum_partial(const __nv_bfloat16* __restrict__ Hh,
                               const __nv_bfloat16* __restrict__ Hl,
                               float* __restrict__ colp)
{
    const int c2 = (blockIdx.x * 128 + threadIdx.x) * 2;   // column pair
    const int r0 = blockIdx.y * 512;
    float s0 = 0.0f, s1 = 0.0f;
    for (int r = 0; r < 512; r++) {
        const size_t o = (size_t)(r0 + r) * DD + c2;
        const __nv_bfloat162 vh = *(const __nv_bfloat162*)(Hh + o);
        const __nv_bfloat162 vl = *(const __nv_bfloat162*)(Hl + o);
        s0 += __bfloat162float(vh.x) + __bfloat162float(vl.x);
        s1 += __bfloat162float(vh.y) + __bfloat162float(vl.y);
    }
    colp[blockIdx.y * DD + c2] = s0;
    colp[blockIdx.y * DD + c2 + 1] = s1;
}

__global__ void mean_finalize(const float* __restrict__ colp, float* __restrict__ mean)
{
    const int i = threadIdx.x;
    float s = 0.0f;
    for (int c = 0; c < 128; c++)
        s += colp[c * DD + i];
    mean[i] = s * (1.0f / (float)NROWS);
}

__global__ void trace_kernel(const float* __restrict__ G,
                             const float* __restrict__ mean,
                             float* __restrict__ scalars)
{
    __shared__ float sm[512];
    const int i = threadIdx.x;
    const float m = mean[i];
    sm[i] = G[i * DD + i] * (1.0f / (float)NROWS) - m * m + INV_TEMP;
    __syncthreads();
    for (int s = 256; s > 0; s >>= 1) {
        if (i < s) sm[i] += sm[i + s];
        __syncthreads();
    }
    if (i == 0) {
        const float tr = sm[0];
        scalars[0] = tr;
        scalars[1] = 1.0f / tr;
        scalars[2] = rsqrtf(tr);
    }
}

__global__ void s_kernel(const float* __restrict__ G,
                         const float* __restrict__ mean,
                         const float* __restrict__ scalars,
                         float* __restrict__ S,
                         __nv_bfloat16* __restrict__ Sh, __nv_bfloat16* __restrict__ Sl)
{
    const int i = blockIdx.x, j = threadIdx.x;
    const float invtr = scalars[1];
    float v = G[i * DD + j] * (1.0f / (float)NROWS) - mean[i] * mean[j];
    if (i == j) v += INV_TEMP;
    v *= invtr;
    S[i * DD + j] = v;
    split1(v, Sh[i * DD + j], Sl[i * DD + j]);
}

__global__ void eye_kernel(float* __restrict__ P,
                           __nv_bfloat16* __restrict__ Ph, __nv_bfloat16* __restrict__ Pl)
{
    const int i = blockIdx.x, j = threadIdx.x;
    const float v = (i == j) ? 1.0f : 0.0f;
    P[i * DD + j] = v;
    Ph[i * DD + j] = __float2bfloat16_rn(v);
    Pl[i * DD + j] = __float2bfloat16_rn(0.0f);
}

// mc[j] = rsqrt(tr) * sum_k mean[k] * P[k][j]
__global__ void mc_kernel(const float* __restrict__ mean, const float* __restrict__ P,
                          const float* __restrict__ scalars, float* __restrict__ mc)
{
    const int j = threadIdx.x;
    float s = 0.0f;
    for (int k = 0; k < DD; k++)
        s += mean[k] * P[k * DD + j];
    mc[j] = s * scalars[2];
}

// ---------------------------------------------------------------------------
// Host orchestration
// ---------------------------------------------------------------------------
static void run_layer(const float* W, float* out, bool /*unused*/)
{
    float *covp, *G, *S, *P, *Pn, *colp, *mean, *mc, *scal;
    __nv_bfloat16 *Ah, *Al, *Hh, *Hl, *Wh, *Wl, *Sh, *Sl;
    __nv_bfloat16 *Pah, *Pal, *Pbh, *Pbl, *T1h, *T1l, *T2h, *T2l;
    cudaGetSymbolAddress((void**)&covp, g_covp);
    cudaGetSymbolAddress((void**)&G,    g_G);
    cudaGetSymbolAddress((void**)&S,    g_S);
    cudaGetSymbolAddress((void**)&P,    g_P);
    cudaGetSymbolAddress((void**)&Pn,   g_Pn);
    cudaGetSymbolAddress((void**)&colp, g_colp);
    cudaGetSymbolAddress((void**)&mean, g_mean);
    cudaGetSymbolAddress((void**)&mc,   g_mc);
    cudaGetSymbolAddress((void**)&scal, g_scalars);
    cudaGetSymbolAddress((void**)&Ah,   g_Ah);
    cudaGetSymbolAddress((void**)&Al,   g_Al);
    cudaGetSymbolAddress((void**)&Hh,   g_Hh);
    cudaGetSymbolAddress((void**)&Hl,   g_Hl);
    cudaGetSymbolAddress((void**)&Wh,   g_Wh);
    cudaGetSymbolAddress((void**)&Wl,   g_Wl);
    cudaGetSymbolAddress((void**)&Sh,   g_Sh);
    cudaGetSymbolAddress((void**)&Sl,   g_Sl);
    cudaGetSymbolAddress((void**)&Pah,  g_Pah);
    cudaGetSymbolAddress((void**)&Pal,  g_Pal);
    cudaGetSymbolAddress((void**)&Pbh,  g_Pbh);
    cudaGetSymbolAddress((void**)&Pbl,  g_Pbl);
    cudaGetSymbolAddress((void**)&T1h,  g_T1h);
    cudaGetSymbolAddress((void**)&T1l,  g_T1l);
    cudaGetSymbolAddress((void**)&T2h,  g_T2h);
    cudaGetSymbolAddress((void**)&T2l,  g_T2l);

    const int wBlocks = (DD * DD) / (256 * 4);

    // H = in @ W   (A splits already in g_Ah/g_Al; epilogue writes Hh/Hl)
    split_f32<0><<<wBlocks, 256>>>(W, Wh, Wl, nullptr);
    hgemm<0><<<dim3(4, 512), 256, G1_SMEM>>>(Ah, Al, Wh, Wl,
                                             nullptr, Hh, Hl, nullptr, nullptr);

    // mean from split H
    colsum_partial<<<dim3(2, 128), 128>>>(Hh, Hl, colp);
    mean_finalize<<<1, 512>>>(colp, mean);

    // cov (upper-triangle tiles) -> G -> trace -> S (+split)
    hcov<<<dim3(10, 1, KSPLIT), 256, CV_SMEM>>>(Hh, Hl, covp);
    reduce_cov_sym<<<512, 512>>>(covp, G);
    trace_kernel<<<1, 512>>>(G, mean, scal);
    s_kernel<<<512, 512>>>(G, mean, scal, S, Sh, Sl);

    // Newton-Schulz (tensor cores)
    eye_kernel<<<512, 512>>>(P, Pah, Pal);
    float* Pf = P; float* Pg = Pn;
    __nv_bfloat16 *ah = Pah, *al = Pal, *bh = Pbh, *bl = Pbl;
    for (int t = 0; t < NS_ITERS; t++) {
        ns_pair<<<dim3(8, 8, 2), 128>>>(ah, al, Sh, Sl, T1h, T1l, T2h, T2l);
        ns_update<<<dim3(8, 8), 128>>>(T2h, T2l, T1h, T1l, Pf, Pg, bh, bl);
        { float* t0 = Pf; Pf = Pg; Pg = t0; }
        { __nv_bfloat16* t1 = ah; ah = bh; bh = t1; }
        { __nv_bfloat16* t2 = al; al = bl; bl = t2; }
    }

    // out = (H @ P) * rsqrt(tr) - mean @ P * rsqrt(tr); splits of out -> Ah/Al
    mc_kernel<<<1, 512>>>(mean, Pf, scal, mc);
    hgemm<1><<<dim3(4, 512), 256, G1_SMEM>>>(Hh, Hl, ah, al,
                                             out, Ah, Al, scal, mc);
}

extern "C" void kernel_launch(void* const* d_in, const int* in_sizes, int n_in,
                              void* d_out, int out_size)
{
    (void)in_sizes; (void)n_in; (void)out_size;
    const float* x  = (const float*)d_in[0];
    const float* W0 = (const float*)d_in[1];
    const float* W1 = (const float*)d_in[2];
    const float* W2 = (const float*)d_in[3];
    float* out = (float*)d_out;

    cudaFuncSetAttribute(hgemm<0>, cudaFuncAttributeMaxDynamicSharedMemorySize, G1_SMEM);
    cudaFuncSetAttribute(hgemm<1>, cudaFuncAttributeMaxDynamicSharedMemorySize, G1_SMEM);
    cudaFuncSetAttribute(hcov,     cudaFuncAttributeMaxDynamicSharedMemorySize, CV_SMEM);

    __nv_bfloat16 *Ah, *Al;
    cudaGetSymbolAddress((void**)&Ah, g_Ah);
    cudaGetSymbolAddress((void**)&Al, g_Al);

    // initial split of x into the layer-chain input buffers
    split_f32<0><<<(NROWS * DD) / (256 * 4), 256>>>(x, Ah, Al, nullptr);

    run_layer(W0, out, false);
    run_layer(W1, out + (size_t)NROWS * DD, false);
    run_layer(W2, out + (size_t)2 * NROWS * DD, false);
}